// round 14
// baseline (speedup 1.0000x reference)
#include <cuda_runtime.h>
#include <cstdint>

#define SMALL_VAL (-1000.0f)
#define FULLM 0xffffffffu

// Allocation-free scratch.
__device__ float g_partials[8192];
__device__ int   g_perm[8192];
__device__ int   g_done;          // zero-init; last warp resets to 0 each run

// ---------- packed f32x2 helpers (Blackwell; ptxas won't auto-fuse) ----------
__device__ __forceinline__ unsigned long long pack2(float x, float y) {
    unsigned long long r;
    asm("mov.b64 %0, {%1, %2};" : "=l"(r) : "f"(x), "f"(y));
    return r;
}
__device__ __forceinline__ void unpack2(unsigned long long v, float& x, float& y) {
    asm("mov.b64 {%0, %1}, %2;" : "=f"(x), "=f"(y) : "l"(v));
}
__device__ __forceinline__ unsigned long long ffma2(unsigned long long a,
                                                    unsigned long long b,
                                                    unsigned long long c) {
    unsigned long long d;
    asm("fma.rn.f32x2 %0, %1, %2, %3;" : "=l"(d) : "l"(a), "l"(b), "l"(c));
    return d;
}
__device__ __forceinline__ unsigned long long fmul2(unsigned long long a,
                                                    unsigned long long b) {
    unsigned long long d;
    asm("mul.rn.f32x2 %0, %1, %2;" : "=l"(d) : "l"(a), "l"(b));
    return d;
}
__device__ __forceinline__ unsigned long long fadd2(unsigned long long a,
                                                    unsigned long long b) {
    unsigned long long d;
    asm("add.rn.f32x2 %0, %1, %2;" : "=l"(d) : "l"(a), "l"(b));
    return d;
}

// ============================================================================
// Rank permutation: g_perm[rank] = batch, rank by seq_len descending (stable).
// Warp s pairs chains (rank s, rank B-1-s): sum of lengths ~const per warp ->
// automatic per-warp balance; scheduling only, value order-independent.
// ============================================================================
__global__ void crf_perm_kernel(const int* __restrict__ seq_len, int B)
{
    __shared__ int ns[4096];
    const bool use_sh = (B <= 4096);
    if (use_sh) {
        for (int i = threadIdx.x; i < B; i += blockDim.x) ns[i] = seq_len[i];
        __syncthreads();
    }
    int i = blockIdx.x * blockDim.x + threadIdx.x;
    if (i >= B) return;
    int ni = use_sh ? ns[i] : seq_len[i];
    int r = 0;
    #pragma unroll 4
    for (int j = 0; j < B; j++) {
        int nj = use_sh ? ns[j] : seq_len[j];
        r += (nj > ni) || (nj == ni && j < i);
    }
    g_perm[r] = i;
}

// ============================================================================
// Forward CRF: 128-thread blocks = 4 independent warps; EACH WARP RUNS TWO
// CHAINS (batch elements) interleaved in one instruction stream: chain B's
// ffma2 stream covers chain A's LDS/chain latency (intra-warp ILP) instead
// of the phase-locked warp pair that capped issue at 34% at 1 chain/warp.
// LDS are STREAMED (not front-batched): the other chain provides the overlap,
// keeping live registers ~195 (front-batching was ~250, spill-risk).
//
// Lane l owns columns c0 = l, c1 = l + 32 for both chains. E = exp(trans)
// SHARED by the chains: 31 k-pairs x 2 cols = 124 regs (k-pair 31 dropped:
// E rows 62/63 = exp(-10000) = 0, products provably zero).
// Linear-domain recursion per chain:
//   a_t[k'] = (sum_k a_{t-1}[k] * E[k][k']) * exp(obs_t[k']) * 2^{-e_t}
// exp(pred) computed AT LOAD (prefetch, depth 4) so MUFU is off the critical
// path. Rescale exponent from a_prev[0], exact integer accumulation, folded
// in at the end as etot*ln2. Step 1 in exact log domain.
// One __syncwarp per pair-step. Last-finishing warp reduces.
// ============================================================================
__global__ void __launch_bounds__(128, 1) crf_forward_kernel(
    const float* __restrict__ pred,
    const int*   __restrict__ ref,
    const int*   __restrict__ seq_len,
    const float* __restrict__ trans,
    float* __restrict__ out,
    int B, int T, int L)
{
    __shared__ float Tsh[64 * 64];
    __shared__ __align__(16) float abuf[4][2][2][64];  // [warp][chain][cur][64]

    const int w  = threadIdx.x >> 5;
    const int l  = threadIdx.x & 31;
    const int c0 = l;
    const int c1 = l + 32;
    const int W  = (B + 1) / 2;               // active warps
    const int s  = blockIdx.x * 4 + w;        // warp slot

    // ---- load transitions (ALL threads participate, then inactive retire) ----
    {
        const float4* src = (const float4*)trans;
        float4* dst = (float4*)Tsh;
        for (int i = threadIdx.x; i < 1024; i += 128) dst[i] = src[i];
    }
    __syncthreads();
    if (s >= W) return;                       // safe: barrier already passed

    const int rankA = s;
    const int rankB = B - 1 - s;
    const bool realB = (rankB != rankA);      // B odd midpoint guard
    const int bA = g_perm[rankA];
    const int bB = realB ? g_perm[rankB] : bA;
    const int nA = seq_len[bA];
    const int nB = realB ? seq_len[bB] : 1;
    const size_t bTA = (size_t)bA * T;
    const size_t bTB = (size_t)bB * T;

    // ---- E columns c0, c1 (31 k-pairs; pair 31 is zero) ----
    unsigned long long E0[31], E1[31];
    #pragma unroll
    for (int p = 0; p < 31; p++) {
        E0[p] = pack2(__expf(Tsh[(2 * p) * 64 + c0]),
                      __expf(Tsh[(2 * p + 1) * 64 + c0]));
        E1[p] = pack2(__expf(Tsh[(2 * p) * 64 + c1]),
                      __expf(Tsh[(2 * p + 1) * 64 + c1]));
    }

    // ---- step 1 per chain (obs row 1 = pred row 0), exact log-domain LSE ----
    float m1A, m1B;
    {
        float mC0 = -3.4e38f, mC1 = -3.4e38f;
        #pragma unroll 8
        for (int k = 0; k < 64; k++) {
            float init = (k == 62) ? 0.0f : SMALL_VAL;   // b_s (start = 62)
            mC0 = fmaxf(mC0, init + Tsh[k * 64 + c0]);
            mC1 = fmaxf(mC1, init + Tsh[k * 64 + c1]);
        }
        float sC0 = 0.0f, sC1 = 0.0f;
        #pragma unroll 8
        for (int k = 0; k < 64; k++) {
            float init = (k == 62) ? 0.0f : SMALL_VAL;
            sC0 += __expf(init + Tsh[k * 64 + c0] - mC0);
            sC1 += __expf(init + Tsh[k * 64 + c1] - mC1);
        }
        float l0 = mC0 + __logf(sC0);        // LSE(init + T[:,c0]) (obs excl.)
        float l1 = mC1 + __logf(sC1);
        // chain A
        float oA0 = pred[bTA * L + c0];
        float oA1 = (c1 < L) ? pred[bTA * L + c1] : SMALL_VAL;
        float aA0 = oA0 + l0, aA1 = oA1 + l1;
        float mm = fmaxf(aA0, aA1);
        #pragma unroll
        for (int o = 16; o > 0; o >>= 1)
            mm = fmaxf(mm, __shfl_xor_sync(FULLM, mm, o));
        m1A = mm;
        abuf[w][0][0][c0] = __expf(aA0 - m1A);
        abuf[w][0][0][c1] = __expf(aA1 - m1A);
        // chain B
        float oB0 = pred[bTB * L + c0];
        float oB1 = (c1 < L) ? pred[bTB * L + c1] : SMALL_VAL;
        float aB0 = oB0 + l0, aB1 = oB1 + l1;
        float mb = fmaxf(aB0, aB1);
        #pragma unroll
        for (int o = 16; o > 0; o >>= 1)
            mb = fmaxf(mb, __shfl_xor_sync(FULLM, mb, o));
        m1B = mb;
        abuf[w][1][0][c0] = __expf(aB0 - m1B);
        abuf[w][1][0][c1] = __expf(aB1 - m1B);
    }
    __syncwarp();

    // ---- main loops: S_X = n_X - 1 steps ----
    const int SA = nA - 1, SB = nB - 1;
    int etotA = 0, etotB = 0;
    int curA = 0, curB = 0;

    // depth-4 prefetch of EXP'd pred rows (exp at load: MUFU off hot path)
    float bA0[4], bA1[4], bB0[4], bB1[4];
    #pragma unroll
    for (int j = 0; j < 4; j++) {
        bA0[j] = (j < SA) ? __expf(pred[(bTA + 1 + j) * L + c0]) : 0.0f;
        bA1[j] = (j < SA && c1 < L) ? __expf(pred[(bTA + 1 + j) * L + c1]) : 0.0f;
        bB0[j] = (j < SB) ? __expf(pred[(bTB + 1 + j) * L + c0]) : 0.0f;
        bB1[j] = (j < SB && c1 < L) ? __expf(pred[(bTB + 1 + j) * L + c1]) : 0.0f;
    }

    // One chain's recursion step; LDS streamed (other chain covers latency).
    auto chain_step = [&](int chain, int& cur, int& etot,
                          float* b0, float* b1, int q, int j,
                          size_t bT, int S) {
        const ulonglong2* a2 = (const ulonglong2*)(&abuf[w][chain][cur][0]);
        ulonglong2 v0 = a2[0];

        int e = ((int)(v0.x >> 23) & 255) - 127;         // lane-uniform
        e = max(-60, min(60, e));
        float scale = __int_as_float((127 - e) << 23);   // 2^{-e}, exact
        float ps0 = b0[j] * scale, ps1 = b1[j] * scale;

        int row = q + 5;                                 // refill depth-4 slot
        float nf0 = 0.0f, nf1 = 0.0f;
        if (row <= S) {
            nf0 = __expf(pred[(bT + row) * L + c0]);
            if (c1 < L) nf1 = __expf(pred[(bT + row) * L + c1]);
        }

        unsigned long long A0[4], A1[4];
        A0[0] = fmul2(v0.x, E0[0]);  A1[0] = fmul2(v0.x, E1[0]);
        A0[1] = fmul2(v0.y, E0[1]);  A1[1] = fmul2(v0.y, E1[1]);
        {
            ulonglong2 v = a2[1];
            A0[2] = fmul2(v.x, E0[2]);  A1[2] = fmul2(v.x, E1[2]);
            A0[3] = fmul2(v.y, E0[3]);  A1[3] = fmul2(v.y, E1[3]);
        }
        #pragma unroll
        for (int q4 = 2; q4 < 16; q4++) {
            ulonglong2 v = a2[q4];
            int p0 = 2 * q4, p1 = 2 * q4 + 1;
            A0[p0 & 3] = ffma2(v.x, E0[p0], A0[p0 & 3]);
            A1[p0 & 3] = ffma2(v.x, E1[p0], A1[p0 & 3]);
            if (p1 < 31) {      // pair 31 (k=62,63): E rows are exactly 0
                A0[p1 & 3] = ffma2(v.y, E0[p1], A0[p1 & 3]);
                A1[p1 & 3] = ffma2(v.y, E1[p1], A1[p1 & 3]);
            }
        }
        unsigned long long r0 = fadd2(fadd2(A0[0], A0[1]), fadd2(A0[2], A0[3]));
        unsigned long long r1 = fadd2(fadd2(A1[0], A1[1]), fadd2(A1[2], A1[3]));
        float x0, y0, x1, y1;
        unpack2(r0, x0, y0);
        unpack2(r1, x1, y1);

        abuf[w][chain][cur ^ 1][c0] = (x0 + y0) * ps0;
        abuf[w][chain][cur ^ 1][c1] = (x1 + y1) * ps1;
        etot += e;
        b0[j] = nf0;
        b1[j] = nf1;
        cur ^= 1;
    };

    const int Smax = (SA > SB) ? SA : SB;
    for (int q0 = 0; q0 < Smax; q0 += 4) {
        #pragma unroll
        for (int j = 0; j < 4; j++) {
            int q = q0 + j;
            if (q < SA) chain_step(0, curA, etotA, bA0, bA1, q, j, bTA, SA);
            if (q < SB) chain_step(1, curB, etotB, bB0, bB1, q, j, bTB, SB);
            if (q < Smax) __syncwarp();
        }
    }

    // ---- final step per chain: only end column 63 (lane 31, c1) matters ----
    auto final_step = [&](int chain, int cur, int etot, float m1) -> float {
        const ulonglong2* a2 = (const ulonglong2*)(&abuf[w][chain][cur][0]);
        unsigned long long A1[4];
        {
            ulonglong2 v0 = a2[0], v1 = a2[1];
            A1[0] = fmul2(v0.x, E1[0]);
            A1[1] = fmul2(v0.y, E1[1]);
            A1[2] = fmul2(v1.x, E1[2]);
            A1[3] = fmul2(v1.y, E1[3]);
        }
        #pragma unroll
        for (int q4 = 2; q4 < 16; q4++) {
            ulonglong2 v = a2[q4];
            int p0 = 2 * q4, p1 = 2 * q4 + 1;
            A1[p0 & 3] = ffma2(v.x, E1[p0], A1[p0 & 3]);
            if (p1 < 31) A1[p1 & 3] = ffma2(v.y, E1[p1], A1[p1 & 3]);
        }
        unsigned long long r1 = fadd2(fadd2(A1[0], A1[1]), fadd2(A1[2], A1[3]));
        float x1, y1; unpack2(r1, x1, y1);
        float sres = m1 + (float)etot * 0.6931471805599453f + __logf(x1 + y1);
        return __shfl_sync(FULLM, sres, 31);
    };
    float sresA = final_step(0, curA, etotA, m1A);
    float sresB = final_step(1, curB, etotB, m1B);

    // ---- gold path score per chain ----
    auto gold = [&](size_t bT, int n) -> float {
        float rs = 0.0f;
        for (int base = 0; base < n; base += 128) {
            int   rr[4], rp[4];
            float gv[4];
            #pragma unroll
            for (int u = 0; u < 4; u++) {
                int t = base + l + u * 32;
                rr[u] = (t < n) ? ref[bT + t] : 0;
                rp[u] = (t >= 1 && t < n) ? ref[bT + t - 1] : 0;
            }
            #pragma unroll
            for (int u = 0; u < 4; u++) {
                int t = base + l + u * 32;
                gv[u] = (t < n) ? pred[(bT + t) * L + rr[u]] : 0.0f;
            }
            #pragma unroll
            for (int u = 0; u < 4; u++) {
                int t = base + l + u * 32;
                if (t < n) {
                    rs += gv[u];
                    if (t >= 1) rs += Tsh[rp[u] * 64 + rr[u]];
                }
            }
        }
        if (l == 0) {
            rs += Tsh[62 * 64 + ref[bT + 0]];        // start -> ref[0]
            rs += Tsh[ref[bT + n - 1] * 64 + 63];    // ref[n-1] -> end
        }
        #pragma unroll
        for (int o = 16; o > 0; o >>= 1)             // deterministic butterfly
            rs += __shfl_xor_sync(FULLM, rs, o);
        return rs;
    };
    float goldA = gold(bTA, nA);
    float goldB = realB ? gold(bTB, nB) : 0.0f;

    if (l == 0) {
        g_partials[bA] = sresA - goldA;
        if (realB) g_partials[bB] = sresB - goldB;
    }

    // ---- last-finishing warp does the deterministic final reduction ----
    __threadfence();
    int cnt = 1 + (realB ? 1 : 0);
    unsigned is_last = 0;
    if (l == 0) is_last = (atomicAdd(&g_done, cnt) + cnt == B);
    is_last = __shfl_sync(FULLM, is_last, 0);
    if (is_last) {
        volatile float* gp = g_partials;
        float v = 0.0f;
        for (int i = l; i < B; i += 32) v += gp[i];   // fixed order per lane
        #pragma unroll
        for (int o = 16; o > 0; o >>= 1)
            v += __shfl_xor_sync(FULLM, v, o);        // deterministic
        if (l == 0) {
            out[0] = v;
            g_done = 0;                               // graph-replay reset
        }
    }
}

extern "C" void kernel_launch(void* const* d_in, const int* in_sizes, int n_in,
                              void* d_out, int out_size)
{
    const float* pred = (const float*)d_in[0];
    const int*   ref  = (const int*)d_in[1];
    const int*   seq  = (const int*)d_in[2];
    const float* trn  = (const float*)d_in[3];

    int B = in_sizes[2];                 // seq_len has B elements
    int T = in_sizes[1] / B;             // ref is B*T
    int L = in_sizes[0] / in_sizes[1];   // pred is B*T*L

    int W    = (B + 1) / 2;              // warps (2 chains each)
    int nblk = (W + 3) / 4;              // 128 for B=1024
    crf_perm_kernel<<<(B + 63) / 64, 64>>>(seq, B);
    crf_forward_kernel<<<nblk, 128>>>(pred, ref, seq, trn,
                                      (float*)d_out, B, T, L);
}